// round 17
// baseline (speedup 1.0000x reference)
#include <cuda_runtime.h>
#include <cstdint>
#include <cstddef>

#define TT 1024
#define BB 64
#define DD 512
#define HH 512

// Recurrence partition: NI batch-groups (clusters) x NJ hidden-slices
#define NI 16
#define NJ 8
#define BSL (BB / NI)        // 4 batch rows per group
#define HSL (HH / NJ)        // 64 hidden units per slice
#define RKC 16               // reduce chunks: 8 warps x 2 half-warps
#define SLICE_BYTES (BSL * HSL * 4)
#define HS_BYTES (NJ * SLICE_BYTES)
#define WPAD 516             // Wih row stride in floats (conflict-free)

// Dynamic SMEM layout (byte offsets)
#define SO_MBAR   0                         // 2*NJ mbarriers (128 B)
#define SO_STAGE  128                       // 2*BSL*HSL floats (2 KB)
#define SO_HS     (SO_STAGE + 2048)         // 2*NJ*BSL*HSL floats (16 KB)
#define SO_RED    (SO_HS + 16384)           // BSL*RKC*HSL floats (16 KB)
#define SO_XS     (SO_RED + 16384)          // 2*BSL*DD floats (16 KB)
#define SO_WIH    (SO_XS + 16384)           // HSL*WPAD floats (132096 B)
#define SMEM_TOTAL (SO_WIH + HSL * WPAD * 4)  // 183424 B

// Device scratch (no cudaMalloc allowed)
__device__ float g_Y0[(size_t)TT * BB * HH];

// ---------------------------------------------------------------------------
// PTX helpers
// ---------------------------------------------------------------------------
__device__ __forceinline__ uint32_t smem_u32(const void* p) {
    uint32_t a;
    asm("{ .reg .u64 t; cvta.to.shared.u64 t, %1; cvt.u32.u64 %0, t; }"
        : "=r"(a) : "l"(p));
    return a;
}
__device__ __forceinline__ uint32_t mapa_u32(uint32_t addr, uint32_t rank) {
    uint32_t r;
    asm("mapa.shared::cluster.u32 %0, %1, %2;" : "=r"(r) : "r"(addr), "r"(rank));
    return r;
}
__device__ __forceinline__ void mbar_init(uint32_t mbar, uint32_t cnt) {
    asm volatile("mbarrier.init.shared.b64 [%0], %1;" :: "r"(mbar), "r"(cnt) : "memory");
}
__device__ __forceinline__ void mbar_arrive_expect_tx(uint32_t mbar, uint32_t tx) {
    asm volatile("mbarrier.arrive.expect_tx.shared.b64 _, [%0], %1;"
                 :: "r"(mbar), "r"(tx) : "memory");
}
__device__ __forceinline__ void mbar_wait_parity(uint32_t mbar, uint32_t parity) {
    asm volatile(
        "{\n\t"
        ".reg .pred P;\n\t"
        "WAIT_%=:\n\t"
        "mbarrier.try_wait.parity.acquire.cta.shared::cta.b64 P, [%0], %1, 0x989680;\n\t"
        "@P bra.uni DONE_%=;\n\t"
        "bra.uni WAIT_%=;\n\t"
        "DONE_%=:\n\t"
        "}"
        :: "r"(mbar), "r"(parity) : "memory");
}
__device__ __forceinline__ void bulk_dsmem(uint32_t dst_cluster, uint32_t src_cta,
                                           uint32_t bytes, uint32_t mbar_cluster) {
    asm volatile(
        "cp.async.bulk.shared::cluster.shared::cta.mbarrier::complete_tx::bytes "
        "[%0], [%1], %2, [%3];"
        :: "r"(dst_cluster), "r"(src_cta), "r"(bytes), "r"(mbar_cluster) : "memory");
}
__device__ __forceinline__ void fence_proxy_async_cta() {
    asm volatile("fence.proxy.async.shared::cta;" ::: "memory");
}
__device__ __forceinline__ void ffma2(unsigned long long& d,
                                      unsigned long long a, unsigned long long b) {
    asm("fma.rn.f32x2 %0, %1, %2, %0;" : "+l"(d) : "l"(a), "l"(b));
}
__device__ __forceinline__ float lo_f(unsigned long long v) {
    return __uint_as_float((unsigned int)v);
}
__device__ __forceinline__ float hi_f(unsigned long long v) {
    return __uint_as_float((unsigned int)(v >> 32));
}

// ---------------------------------------------------------------------------
// Fused layer kernel: per-CTA input GEMM (Z = x @ Wih^T) + recurrence.
// Grid (NJ, NI), cluster (NJ,1,1). CTA (j, i): hidden slice [j*64, j*64+64),
// batch rows [i*4, i*4+4), all T steps.
//
// Per step t:
//   1. (top) LDG-prefetch x[t+1] rows into registers (DRAM latency hidden)
//   2. Z-partials: a4 += xs[t&1] @ Wih (SMEM, fp32 FFMA2) — BEFORE the wait,
//      fills the idle window while peers' h slices arrive.
//   3. wait my slice's h(t-1) 1KB delivery; h-partials: a4 += hs @ Whh(regs).
//   4. STS x[t+1] into xs[(t+1)&1]; red-store; __syncthreads; reduce.
//   5. val = tanh(acc + bias); write Y; stage; __syncthreads; 1KB bulk ship.
//
// Whh slice in registers (64 u64/lane, 4 outputs x 32k half-warp chunk, each
// 16B h-load feeds 8 FFMA2 — the R15 structure). Wih slice in SMEM, rows
// padded to 516 floats => 16-lane column reads are bank-conflict-free.
// ---------------------------------------------------------------------------
__global__ __launch_bounds__(256, 1) __cluster_dims__(NJ, 1, 1)
void fused_layer_kernel(
    const float* __restrict__ X,    const float* __restrict__ Wih,
    const float* __restrict__ bih,  const float* __restrict__ Whh,
    const float* __restrict__ bhh,  float* __restrict__ Y)
{
    extern __shared__ char smem[];
    float* s_stage = (float*)(smem + SO_STAGE);            // [2][BSL][HSL]
    float* s_hs    = (float*)(smem + SO_HS);               // [2][NJ][BSL][HSL]
    float* s_red   = (float*)(smem + SO_RED);              // [BSL][RKC][HSL]
    float* s_xs    = (float*)(smem + SO_XS);               // [2][BSL][DD]
    float* s_wih   = (float*)(smem + SO_WIH);              // [HSL][WPAD]

    const int j    = blockIdx.x;                 // hidden slice = cluster rank
    const int i    = blockIdx.y;                 // batch group
    const int tid  = threadIdx.x;
    const int w    = tid >> 5;                   // warp 0..7 = slice/k-chunk
    const int lane = tid & 31;
    const int hh   = lane >> 4;                  // half-warp = 32-k sub-chunk
    const int ll   = lane & 15;
    const int b0   = i * BSL;

    const uint32_t smem_base  = smem_u32(smem);
    const uint32_t mbar_base  = smem_base + SO_MBAR;
    const uint32_t stage_base = smem_base + SO_STAGE;
    const uint32_t hs_base    = smem_base + SO_HS;

    if (tid == 0) {
#pragma unroll
        for (int ph = 0; ph < 2; ph++)
#pragma unroll
            for (int s = 0; s < NJ; s++) {
                const uint32_t mb = mbar_base + (uint32_t)(ph * NJ + s) * 8;
                mbar_init(mb, 1);
                mbar_arrive_expect_tx(mb, SLICE_BYTES);
            }
    }

    // Prologue loads: Wih slice (64x512 -> padded SMEM) and xs[0] = x[0] rows.
    {
        const float* wsrc = Wih + (size_t)(j * HSL) * DD;
        for (int v = tid; v < HSL * (DD / 4); v += 256) {   // 8192 float4
            int r  = v >> 7;
            int c4 = (v & 127) * 4;
            float4 t4 = *(const float4*)(wsrc + (size_t)r * DD + c4);
            *(float4*)&s_wih[r * WPAD + c4] = t4;
        }
        for (int v = tid; v < BSL * (DD / 4); v += 256) {   // 512 float4
            int b  = v >> 7;
            int c4 = (v & 127) * 4;
            float4 t4 = *(const float4*)(X + ((size_t)0 * BB + b0 + b) * DD + c4);
            *(float4*)&s_xs[b * DD + c4] = t4;
        }
    }
    __syncthreads();
    asm volatile("barrier.cluster.arrive.aligned;" ::: "memory");
    asm volatile("barrier.cluster.wait.aligned;"  ::: "memory");

    uint32_t my_peer_hs = 0, my_peer_mb = 0;
    if (tid < NJ) {
        my_peer_hs = mapa_u32(hs_base,   (uint32_t)tid);
        my_peer_mb = mapa_u32(mbar_base, (uint32_t)tid);
    }

    // Whh weights for my FOUR outputs (j*64 + ll + o*16), k in [w*64+hh*32,+32)
    unsigned long long w4[4][16];
    {
        const int k0 = w * 64 + hh * 32;
#pragma unroll
        for (int o = 0; o < 4; o++) {
            const float* wrow = Whh + (size_t)(j * HSL + ll + o * 16) * HH + k0;
#pragma unroll
            for (int q = 0; q < 8; q++) {
                float4 v = *(const float4*)(wrow + q * 4);
                w4[o][q * 2 + 0] = (unsigned long long)__float_as_uint(v.x)
                                 | ((unsigned long long)__float_as_uint(v.y) << 32);
                w4[o][q * 2 + 1] = (unsigned long long)__float_as_uint(v.z)
                                 | ((unsigned long long)__float_as_uint(v.w) << 32);
            }
        }
    }

    // Epilogue mapping: thread tid owns output (rb, rjj)
    const int rb  = tid >> 6;
    const int rjj = tid & 63;
    const int brow = b0 + rb;
    const int jg   = j * HSL + rjj;
    const size_t y_off = (size_t)brow * HH + jg;
    const float bias_r = __ldg(bih + jg) + __ldg(bhh + jg);

    // x prefetch mapping: thread loads 2 float4 of x[t+1]
    const int xv0 = tid * 2, xv1 = tid * 2 + 1;
    const int xr0 = xv0 >> 7, xc0 = (xv0 & 127) * 4;
    const int xr1 = xv1 >> 7, xc1 = (xv1 & 127) * 4;

    // My slice barrier per phase; my reduce chunk
    const uint32_t mbP0 = mbar_base + (uint32_t)(0 * NJ + w) * 8;
    const uint32_t mbP1 = mbar_base + (uint32_t)(1 * NJ + w) * 8;
    const int rc = w * 2 + hh;
    const int kz = hh * 32;        // my 32-k window within warp-chunk... (see below)

    int par[2] = {0, 0};

    for (int t = 0; t < TT; t++) {
        const int ph = t & 1;

        // (1) prefetch x[t+1] into registers
        float4 px0, px1;
        if (t + 1 < TT) {
            px0 = __ldcs((const float4*)(X + ((size_t)(t + 1) * BB + b0 + xr0) * DD + xc0));
            px1 = __ldcs((const float4*)(X + ((size_t)(t + 1) * BB + b0 + xr1) * DD + xc1));
        }

        // (2) Z-partials from xs[ph] and SMEM Wih — independent of h, pre-wait.
        // My k-window: [w*64 + hh*32, +32).
        unsigned long long a4[4][BSL];
#pragma unroll
        for (int o = 0; o < 4; o++)
#pragma unroll
            for (int b = 0; b < BSL; b++) a4[o][b] = 0ull;
        {
            const float* xbase = s_xs + (size_t)ph * BSL * DD + (w * 64 + kz);
            const float* wbase = s_wih + (w * 64 + kz);
#pragma unroll
            for (int q = 0; q < 8; q++) {
                unsigned long long wz[4][2];
#pragma unroll
                for (int o = 0; o < 4; o++) {
                    ulonglong2 wv = *(const ulonglong2*)
                        (wbase + (size_t)(ll + o * 16) * WPAD + q * 4);
                    wz[o][0] = wv.x; wz[o][1] = wv.y;
                }
#pragma unroll
                for (int b = 0; b < BSL; b++) {
                    ulonglong2 xv = *(const ulonglong2*)(xbase + (size_t)b * DD + q * 4);
#pragma unroll
                    for (int o = 0; o < 4; o++) {
                        ffma2(a4[o][b], xv.x, wz[o][0]);
                        ffma2(a4[o][b], xv.y, wz[o][1]);
                    }
                }
            }
        }

        // (3) h-partials (t > 0): wait my slice's delivery, then accumulate.
        if (t > 0) {
            const uint32_t mb = (ph == 0) ? mbP0 : mbP1;
            const int p = par[ph];
            mbar_wait_parity(mb, p);
            if (lane == 0) mbar_arrive_expect_tx(mb, SLICE_BYTES);
            par[ph] = p ^ 1;

            const float* hbase = s_hs
                + ((size_t)ph * NJ + w) * BSL * HSL + kz;
#pragma unroll
            for (int b = 0; b < BSL; b++) {
                const ulonglong2* hp = (const ulonglong2*)(hbase + (size_t)b * HSL);
#pragma unroll
                for (int q = 0; q < 8; q++) {
                    ulonglong2 hv = hp[q];
#pragma unroll
                    for (int o = 0; o < 4; o++) {
                        ffma2(a4[o][b], hv.x, w4[o][q * 2 + 0]);
                        ffma2(a4[o][b], hv.y, w4[o][q * 2 + 1]);
                    }
                }
            }
        }

        // (4) store x[t+1] to xs[ph^1]; reduce partials across 16 chunks.
        if (t + 1 < TT) {
            float* xd = s_xs + (size_t)(ph ^ 1) * BSL * DD;
            *(float4*)&xd[xr0 * DD + xc0] = px0;
            *(float4*)&xd[xr1 * DD + xc1] = px1;
        }
#pragma unroll
        for (int b = 0; b < BSL; b++)
#pragma unroll
            for (int o = 0; o < 4; o++)
                s_red[((size_t)b * RKC + rc) * HSL + ll + o * 16] =
                    lo_f(a4[o][b]) + hi_f(a4[o][b]);
        __syncthreads();

        float acc = 0.0f;
#pragma unroll
        for (int c = 0; c < RKC; c++)
            acc += s_red[((size_t)rb * RKC + c) * HSL + rjj];

        // (5) tanh + output + stage + ship
        float val = tanhf(acc + bias_r);
        Y[(size_t)t * BB * HH + y_off] = val;

        if (t + 1 < TT) {
            s_stage[((size_t)ph * BSL + rb) * HSL + rjj] = val;
            __syncthreads();
            if (tid < NJ) {
                fence_proxy_async_cta();
                const uint32_t src = stage_base + (uint32_t)ph * SLICE_BYTES;
                const uint32_t dst = my_peer_hs
                    + (uint32_t)(ph ^ 1) * HS_BYTES + (uint32_t)j * SLICE_BYTES;
                const uint32_t mb  = my_peer_mb + (uint32_t)((ph ^ 1) * NJ + j) * 8;
                bulk_dsmem(dst, src, SLICE_BYTES, mb);
            }
        } else {
            __syncthreads();
        }
    }

    asm volatile("barrier.cluster.arrive.aligned;" ::: "memory");
    asm volatile("barrier.cluster.wait.aligned;"  ::: "memory");
}

// ---------------------------------------------------------------------------
extern "C" void kernel_launch(void* const* d_in, const int* in_sizes, int n_in,
                              void* d_out, int out_size)
{
    const float* Xt   = (const float*)d_in[0];
    const float* ihW0 = (const float*)d_in[1];
    const float* ihB0 = (const float*)d_in[2];
    const float* hhW0 = (const float*)d_in[3];
    const float* hhB0 = (const float*)d_in[4];
    const float* ihW1 = (const float*)d_in[5];
    const float* ihB1 = (const float*)d_in[6];
    const float* hhW1 = (const float*)d_in[7];
    const float* hhB1 = (const float*)d_in[8];
    float* out = (float*)d_out;

    float* y0p = nullptr;
    cudaGetSymbolAddress((void**)&y0p, g_Y0);

    cudaFuncSetAttribute(fused_layer_kernel,
                         cudaFuncAttributeMaxDynamicSharedMemorySize, SMEM_TOTAL);

    dim3 rgrid(NJ, NI);   // (8, 16) -> 128 CTAs, clusters of 8

    // Layer 0: Y0 = ElmanLayer(Xt; ihW0, ihB0, hhW0, hhB0)
    fused_layer_kernel<<<rgrid, 256, SMEM_TOTAL>>>(Xt, ihW0, ihB0, hhW0, hhB0, y0p);
    // Layer 1: out = ElmanLayer(Y0; ihW1, ihB1, hhW1, hhB1)
    fused_layer_kernel<<<rgrid, 256, SMEM_TOTAL>>>(y0p, ihW1, ihB1, hhW1, hhB1, out);
}